// round 2
// baseline (speedup 1.0000x reference)
#include <cuda_runtime.h>
#include <math.h>

#define R_ROIS   1000
#define NCH      256
#define POOLP    7
#define KCONV    (NCH*POOLP*POOLP)   // 12544
#define HID      1024

// ---------------- scratch (static device globals; no allocation) ----------------
__device__ float g_pooled[(size_t)R_ROIS * KCONV];   // ~50 MB
__device__ float g_y [R_ROIS * HID];
__device__ float g_h1[R_ROIS * HID];
__device__ float g_h2[R_ROIS * HID];

// ---------------- ROI align ----------------
// pooled[r][c][py][px], matching conv_w flatten (o, c, h, w)
__global__ void roi_align_kernel(const float* __restrict__ f2,
                                 const float* __restrict__ f3,
                                 const float* __restrict__ f4,
                                 const float* __restrict__ f5,
                                 const float* __restrict__ rois)
{
    int idx = blockIdx.x * blockDim.x + threadIdx.x;
    const int total = R_ROIS * NCH * POOLP * POOLP;
    if (idx >= total) return;

    int px = idx % POOLP;
    int py = (idx / POOLP) % POOLP;
    int c  = (idx / (POOLP * POOLP)) % NCH;
    int r  = idx / (NCH * POOLP * POOLP);

    float x1 = rois[r * 4 + 0];
    float y1 = rois[r * 4 + 1];
    float x2 = rois[r * 4 + 2];
    float y2 = rois[r * 4 + 3];

    // level assignment: clip(round(log2(sqrt(area)/224)) + 4, 2, 5)
    float area = (y2 - y1) * (x2 - x1);
    float lf = rintf(log2f(sqrtf(area) * (1.0f / 224.0f))) + 4.0f;
    lf = fminf(fmaxf(lf, 2.0f), 5.0f);
    int lvl = (int)lf;

    const float* f = (lvl == 2) ? f2 : (lvl == 3) ? f3 : (lvl == 4) ? f4 : f5;
    int H = 256 >> (lvl - 2);

    // normalized box (y1,x1,y2,x2)/1024
    const float inv = 1.0f / 1024.0f;
    float by1 = y1 * inv, bx1 = x1 * inv, by2 = y2 * inv, bx2 = x2 * inv;

    float ty = (float)py * (1.0f / 6.0f);
    float tx = (float)px * (1.0f / 6.0f);
    float Hm1 = (float)(H - 1);
    float ys = (by1 + (by2 - by1) * ty) * Hm1;
    float xs = (bx1 + (bx2 - bx1) * tx) * Hm1;

    bool valid = (ys >= 0.0f) && (ys <= Hm1) && (xs >= 0.0f) && (xs <= Hm1);

    float yf = floorf(ys), xf = floorf(xs);
    float wy = ys - yf,    wx = xs - xf;

    int y0  = min(max((int)yf,     0), H - 1);
    int y1i = min(max((int)yf + 1, 0), H - 1);
    int x0  = min(max((int)xf,     0), H - 1);
    int x1i = min(max((int)xf + 1, 0), H - 1);

    const float* fc = f + (size_t)c * H * H;
    float v00 = fc[y0  * H + x0 ];
    float v01 = fc[y0  * H + x1i];
    float v10 = fc[y1i * H + x0 ];
    float v11 = fc[y1i * H + x1i];

    float val = v00 * (1.0f - wy) * (1.0f - wx)
              + v01 * (1.0f - wy) * wx
              + v10 * wy * (1.0f - wx)
              + v11 * wy * wx;

    g_pooled[(size_t)r * KCONV + c * (POOLP * POOLP) + py * POOLP + px] =
        valid ? val : 0.0f;
}

// ---------------- NT GEMM body: C[m,n] = dot(A[m,:], B[n,:]) + epilogue ----------------
// A: [M,K] row-major, B: [N,K] row-major.
// Tile: 128(M) x 64(N), TK=16, 256 threads, 8x4 per thread.
// MODE 0: batchnorm epilogue; MODE 1: relu(x + bias)
template<int MODE>
__device__ __forceinline__
void gemm_nt_body(const float* __restrict__ A,
                  const float* __restrict__ B,
                  float* __restrict__ Cout,
                  int M, int N, int K,
                  const float* __restrict__ bias,
                  const float* __restrict__ gamma,
                  const float* __restrict__ beta,
                  const float* __restrict__ mean,
                  const float* __restrict__ var)
{
    __shared__ float As[16][128 + 4];
    __shared__ float Bs[16][64 + 4];

    int tid = threadIdx.x;
    int m0 = blockIdx.y * 128;
    int n0 = blockIdx.x * 64;

    int tx = tid & 15;      // 0..15 -> N
    int ty = tid >> 4;      // 0..15 -> M

    int lrow = tid >> 2;        // 0..63
    int lk   = (tid & 3) * 4;   // 0,4,8,12

    float acc[8][4];
    #pragma unroll
    for (int i = 0; i < 8; i++)
        #pragma unroll
        for (int j = 0; j < 4; j++) acc[i][j] = 0.0f;

    for (int k0 = 0; k0 < K; k0 += 16) {
        // load A tile: rows m0+lrow and m0+lrow+64
        #pragma unroll
        for (int half = 0; half < 2; half++) {
            int am = m0 + lrow + half * 64;
            float4 a4 = make_float4(0.f, 0.f, 0.f, 0.f);
            if (am < M)
                a4 = *(const float4*)&A[(size_t)am * K + k0 + lk];
            As[lk + 0][lrow + half * 64] = a4.x;
            As[lk + 1][lrow + half * 64] = a4.y;
            As[lk + 2][lrow + half * 64] = a4.z;
            As[lk + 3][lrow + half * 64] = a4.w;
        }
        // load B tile: row n0+lrow (N is multiple of 64 here)
        {
            float4 b4 = *(const float4*)&B[(size_t)(n0 + lrow) * K + k0 + lk];
            Bs[lk + 0][lrow] = b4.x;
            Bs[lk + 1][lrow] = b4.y;
            Bs[lk + 2][lrow] = b4.z;
            Bs[lk + 3][lrow] = b4.w;
        }
        __syncthreads();

        #pragma unroll
        for (int kk = 0; kk < 16; kk++) {
            float a[8], b[4];
            #pragma unroll
            for (int i = 0; i < 8; i++) a[i] = As[kk][ty * 8 + i];
            #pragma unroll
            for (int j = 0; j < 4; j++) b[j] = Bs[kk][tx * 4 + j];
            #pragma unroll
            for (int i = 0; i < 8; i++)
                #pragma unroll
                for (int j = 0; j < 4; j++)
                    acc[i][j] = fmaf(a[i], b[j], acc[i][j]);
        }
        __syncthreads();
    }

    #pragma unroll
    for (int j = 0; j < 4; j++) {
        int n = n0 + tx * 4 + j;
        float bi = bias[n];
        float sc = 1.0f, sh = 0.0f;
        if (MODE == 0) {
            float iv = rsqrtf(var[n] + 0.001f);
            sc = gamma[n] * iv;
            sh = beta[n] - mean[n] * sc;
        }
        #pragma unroll
        for (int i = 0; i < 8; i++) {
            int m = m0 + ty * 8 + i;
            if (m < M) {
                float v = acc[i][j] + bi;
                if (MODE == 0) v = v * sc + sh;
                else           v = fmaxf(v, 0.0f);
                Cout[(size_t)m * N + n] = v;
            }
        }
    }
}

// Thin wrappers binding scratch globals in device code (no host symbol lookups).
__global__ __launch_bounds__(256)
void gemm_conv_kernel(const float* __restrict__ conv_w,
                      const float* __restrict__ conv_b,
                      const float* __restrict__ gamma,
                      const float* __restrict__ beta,
                      const float* __restrict__ mean,
                      const float* __restrict__ var)
{
    gemm_nt_body<0>(g_pooled, conv_w, g_y, R_ROIS, HID, KCONV,
                    conv_b, gamma, beta, mean, var);
}

__global__ __launch_bounds__(256)
void gemm_fc1_kernel(const float* __restrict__ w, const float* __restrict__ b)
{
    gemm_nt_body<1>(g_y, w, g_h1, R_ROIS, HID, HID,
                    b, nullptr, nullptr, nullptr, nullptr);
}

__global__ __launch_bounds__(256)
void gemm_fc2_kernel(const float* __restrict__ w, const float* __restrict__ b)
{
    gemm_nt_body<1>(g_h1, w, g_h2, R_ROIS, HID, HID,
                    b, nullptr, nullptr, nullptr, nullptr);
}

// ---------------- heads: logits, softmax probs, bbox ----------------
__global__ void heads_kernel(const float* __restrict__ cls_w,
                             const float* __restrict__ cls_b,
                             const float* __restrict__ bbox_w,
                             const float* __restrict__ bbox_b,
                             float* __restrict__ out)
{
    int r = blockIdx.x;
    int t = threadIdx.x;   // 128 threads

    float acc[10];
    #pragma unroll
    for (int i = 0; i < 10; i++) acc[i] = 0.0f;

    const float* hrow = &g_h2[(size_t)r * HID];
    for (int k = t; k < HID; k += 128) {
        float h = hrow[k];
        acc[0] = fmaf(h, cls_w[k],        acc[0]);
        acc[1] = fmaf(h, cls_w[HID + k],  acc[1]);
        #pragma unroll
        for (int j = 0; j < 8; j++)
            acc[2 + j] = fmaf(h, bbox_w[(size_t)j * HID + k], acc[2 + j]);
    }

    // warp reduce
    #pragma unroll
    for (int off = 16; off > 0; off >>= 1)
        #pragma unroll
        for (int i = 0; i < 10; i++)
            acc[i] += __shfl_down_sync(0xffffffffu, acc[i], off);

    __shared__ float red[4][10];
    if ((t & 31) == 0)
        #pragma unroll
        for (int i = 0; i < 10; i++) red[t >> 5][i] = acc[i];
    __syncthreads();

    if (t == 0) {
        float s[10];
        #pragma unroll
        for (int i = 0; i < 10; i++)
            s[i] = red[0][i] + red[1][i] + red[2][i] + red[3][i];

        float l0 = s[0] + cls_b[0];
        float l1 = s[1] + cls_b[1];
        out[r * 2 + 0] = l0;
        out[r * 2 + 1] = l1;

        float mx = fmaxf(l0, l1);
        float e0 = expf(l0 - mx), e1 = expf(l1 - mx);
        float inv = 1.0f / (e0 + e1);
        out[2 * R_ROIS + r * 2 + 0] = e0 * inv;
        out[2 * R_ROIS + r * 2 + 1] = e1 * inv;

        #pragma unroll
        for (int j = 0; j < 8; j++)
            out[4 * R_ROIS + r * 8 + j] = s[2 + j] + bbox_b[j];
    }
}

// ---------------- launch ----------------
extern "C" void kernel_launch(void* const* d_in, const int* in_sizes, int n_in,
                              void* d_out, int out_size)
{
    const float* feat2   = (const float*)d_in[0];
    const float* feat3   = (const float*)d_in[1];
    const float* feat4   = (const float*)d_in[2];
    const float* feat5   = (const float*)d_in[3];
    const float* rois    = (const float*)d_in[4];
    const float* conv_w  = (const float*)d_in[5];
    const float* conv_b  = (const float*)d_in[6];
    const float* bn_g    = (const float*)d_in[7];
    const float* bn_b    = (const float*)d_in[8];
    const float* bn_m    = (const float*)d_in[9];
    const float* bn_v    = (const float*)d_in[10];
    const float* fc1_w   = (const float*)d_in[11];
    const float* fc1_b   = (const float*)d_in[12];
    const float* fc2_w   = (const float*)d_in[13];
    const float* fc2_b   = (const float*)d_in[14];
    const float* cls_w   = (const float*)d_in[15];
    const float* cls_b   = (const float*)d_in[16];
    const float* bbox_w  = (const float*)d_in[17];
    const float* bbox_b  = (const float*)d_in[18];
    float* out = (float*)d_out;

    // 1) ROI align
    {
        const int total = R_ROIS * NCH * POOLP * POOLP;
        int threads = 256;
        int blocks = (total + threads - 1) / threads;
        roi_align_kernel<<<blocks, threads>>>(feat2, feat3, feat4, feat5, rois);
    }

    // 2) conv-as-GEMM + BN : y = BN(pooled @ conv_w^T + conv_b)
    dim3 grid(HID / 64, (R_ROIS + 127) / 128);
    gemm_conv_kernel<<<grid, 256>>>(conv_w, conv_b, bn_g, bn_b, bn_m, bn_v);

    // 3) fc1 + relu
    gemm_fc1_kernel<<<grid, 256>>>(fc1_w, fc1_b);

    // 4) fc2 + relu
    gemm_fc2_kernel<<<grid, 256>>>(fc2_w, fc2_b);

    // 5) heads (logits, probs, bbox)
    heads_kernel<<<R_ROIS, 128>>>(cls_w, cls_b, bbox_w, bbox_b, out);
}

// round 8
// speedup vs baseline: 1.3212x; 1.3212x over previous
#include <cuda_runtime.h>
#include <cuda_bf16.h>
#include <math.h>
#include <stdint.h>

#define R_ROIS 1000
#define MPAD   1024
#define NCH    256
#define POOLP  7
#define KCONV  12544
#define HID    1024

// ---------------- scratch (static device globals, ~64MB like passing R2) ---------
__device__ __align__(16) float g_pooled[(size_t)MPAD * KCONV];  // rows 1000..1023 stay 0
__device__ __align__(16) float g_y [(size_t)MPAD * HID];
__device__ __align__(16) float g_h1[(size_t)MPAD * HID];
__device__ __align__(16) float g_h2[(size_t)MPAD * HID];

// ---------------- helpers ----------------
__device__ __forceinline__ void mma16816(float& c0, float& c1, float& c2, float& c3,
                                         uint32_t a0, uint32_t a1, uint32_t a2, uint32_t a3,
                                         uint32_t b0, uint32_t b1) {
    asm volatile("mma.sync.aligned.m16n8k16.row.col.f32.bf16.bf16.f32 "
        "{%0,%1,%2,%3}, {%4,%5,%6,%7}, {%8,%9}, {%0,%1,%2,%3};"
        : "+f"(c0), "+f"(c1), "+f"(c2), "+f"(c3)
        : "r"(a0), "r"(a1), "r"(a2), "r"(a3), "r"(b0), "r"(b1));
}
// split two fp32 into packed (hi, lo) bf16x2 registers; low half = first element
__device__ __forceinline__ void split_pack(float x, float y, uint32_t& hi, uint32_t& lo) {
    __nv_bfloat16 hx = __float2bfloat16(x);
    __nv_bfloat16 hy = __float2bfloat16(y);
    __nv_bfloat16 lx = __float2bfloat16(x - __bfloat162float(hx));
    __nv_bfloat16 ly = __float2bfloat16(y - __bfloat162float(hy));
    hi = (uint32_t)__bfloat16_as_ushort(hx) | ((uint32_t)__bfloat16_as_ushort(hy) << 16);
    lo = (uint32_t)__bfloat16_as_ushort(lx) | ((uint32_t)__bfloat16_as_ushort(ly) << 16);
}

// ---------------- ROI align (fp32 pooled, identical to passing R2) ----------------
__global__ void roi_align_kernel(const float* __restrict__ f2,
                                 const float* __restrict__ f3,
                                 const float* __restrict__ f4,
                                 const float* __restrict__ f5,
                                 const float* __restrict__ rois)
{
    int idx = blockIdx.x * blockDim.x + threadIdx.x;
    const int total = R_ROIS * NCH * POOLP * POOLP;
    if (idx >= total) return;

    int px = idx % POOLP;
    int py = (idx / POOLP) % POOLP;
    int c  = (idx / (POOLP * POOLP)) % NCH;
    int r  = idx / (NCH * POOLP * POOLP);

    float x1 = rois[r * 4 + 0];
    float y1 = rois[r * 4 + 1];
    float x2 = rois[r * 4 + 2];
    float y2 = rois[r * 4 + 3];

    float area = (y2 - y1) * (x2 - x1);
    float lf = rintf(log2f(sqrtf(area) * (1.0f / 224.0f))) + 4.0f;
    lf = fminf(fmaxf(lf, 2.0f), 5.0f);
    int lvl = (int)lf;

    const float* f = (lvl == 2) ? f2 : (lvl == 3) ? f3 : (lvl == 4) ? f4 : f5;
    int H = 256 >> (lvl - 2);

    const float inv = 1.0f / 1024.0f;
    float by1 = y1 * inv, bx1 = x1 * inv, by2 = y2 * inv, bx2 = x2 * inv;

    float ty = (float)py * (1.0f / 6.0f);
    float tx = (float)px * (1.0f / 6.0f);
    float Hm1 = (float)(H - 1);
    float ys = (by1 + (by2 - by1) * ty) * Hm1;
    float xs = (bx1 + (bx2 - bx1) * tx) * Hm1;

    bool valid = (ys >= 0.0f) && (ys <= Hm1) && (xs >= 0.0f) && (xs <= Hm1);

    float yf = floorf(ys), xf = floorf(xs);
    float wy = ys - yf,    wx = xs - xf;

    int y0  = min(max((int)yf,     0), H - 1);
    int y1i = min(max((int)yf + 1, 0), H - 1);
    int x0  = min(max((int)xf,     0), H - 1);
    int x1i = min(max((int)xf + 1, 0), H - 1);

    const float* fc = f + (size_t)c * H * H;
    float v00 = fc[y0  * H + x0 ];
    float v01 = fc[y0  * H + x1i];
    float v10 = fc[y1i * H + x0 ];
    float v11 = fc[y1i * H + x1i];

    float val = v00 * (1.0f - wy) * (1.0f - wx)
              + v01 * (1.0f - wy) * wx
              + v10 * wy * (1.0f - wx)
              + v11 * wy * wx;

    g_pooled[(size_t)r * KCONV + c * (POOLP * POOLP) + py * POOLP + px] =
        valid ? val : 0.0f;
}

// ---------------- HMMA GEMM with on-the-fly 2-term bf16 split --------------------
// C[m,n] = dot(A[m,:], B[n,:]); A,B fp32 row-major (A: [MPAD][K], B: [N][K]).
// Accumulates ah·bh + al·bh + ah·bl in fp32 (residual ~2^-16 relative).
// CTA tile 128Mx64N, K-tile 32. 256 threads = 8 warps (4M x 2N), warp tile 32x32.
// smem words (uint32): Ahi@0 (row stride 20 words), Alo@2560, Bhi@5120, Blo@6400.
// All smem traffic via plain C++ loads/stores (compiler-visible aliasing).
// MODE 0: batchnorm epilogue; MODE 1: relu(x + bias). Outputs fp32.
template<int MODE>
__device__ __forceinline__ void gemm_body(
    const float* __restrict__ A,
    const float* __restrict__ B,
    int K,
    const float* __restrict__ bias,
    const float* __restrict__ gamma, const float* __restrict__ beta,
    const float* __restrict__ mean,  const float* __restrict__ var,
    float* __restrict__ Out)
{
    __shared__ __align__(16) uint32_t sm[7680];   // 30720 bytes

    const int tid = threadIdx.x;
    const int wid = tid >> 5, l = tid & 31;
    const int wm = wid & 3, wn = wid >> 2;     // 4 M-warps x 2 N-warps
    const int lr = l >> 2, lc = (l & 3) * 2;   // groupID, tg*2

    const int m0 = blockIdx.y * 128;
    const int n0 = blockIdx.x * 64;
    const int NKT = K >> 5;

    float acc[2][4][4];
    #pragma unroll
    for (int i = 0; i < 2; i++)
        #pragma unroll
        for (int j = 0; j < 4; j++)
            #pragma unroll
            for (int k = 0; k < 4; k++) acc[i][j][k] = 0.0f;

    for (int kt = 0; kt < NKT; ++kt) {
        // ---- load + split A tile: 128 rows x 32 K fp32 (1024 float4 chunks) ----
        #pragma unroll
        for (int i = 0; i < 4; i++) {
            int q = tid + i * 256;
            int row = q >> 3, ch = q & 7;
            float4 v = *(const float4*)(A + (size_t)(m0 + row) * K + kt * 32 + ch * 4);
            uint32_t h0, l0, h1, l1;
            split_pack(v.x, v.y, h0, l0);
            split_pack(v.z, v.w, h1, l1);
            int w = row * 20 + ch * 2;
            *(uint2*)&sm[w]        = make_uint2(h0, h1);
            *(uint2*)&sm[w + 2560] = make_uint2(l0, l1);
        }
        // ---- load + split B tile: 64 rows x 32 K fp32 (512 chunks) ----
        #pragma unroll
        for (int i = 0; i < 2; i++) {
            int q = tid + i * 256;
            int row = q >> 3, ch = q & 7;
            float4 v = *(const float4*)(B + (size_t)(n0 + row) * K + kt * 32 + ch * 4);
            uint32_t h0, l0, h1, l1;
            split_pack(v.x, v.y, h0, l0);
            split_pack(v.z, v.w, h1, l1);
            int w = 5120 + row * 20 + ch * 2;
            *(uint2*)&sm[w]        = make_uint2(h0, h1);
            *(uint2*)&sm[w + 1280] = make_uint2(l0, l1);
        }
        __syncthreads();

        #pragma unroll
        for (int h = 0; h < 2; ++h) {
            // B fragments (words): base 5120, row stride 20, k offset h*8 + lc/2
            uint32_t bh[4][2], bl[4][2];
            #pragma unroll
            for (int nf = 0; nf < 4; nf++) {
                int r0 = 5120 + (wn * 32 + nf * 8 + lr) * 20 + h * 8 + (lc >> 1);
                bh[nf][0] = sm[r0];
                bh[nf][1] = sm[r0 + 4];          // k + 8
                bl[nf][0] = sm[r0 + 1280];
                bl[nf][1] = sm[r0 + 1280 + 4];
            }
            #pragma unroll
            for (int mf = 0; mf < 2; mf++) {
                int r0 = (wm * 32 + mf * 16 + lr) * 20 + h * 8 + (lc >> 1);
                uint32_t a0 = sm[r0];
                uint32_t a1 = sm[r0 + 160];      // row + 8
                uint32_t a2 = sm[r0 + 4];        // k + 8
                uint32_t a3 = sm[r0 + 164];
                uint32_t e0 = sm[r0 + 2560];
                uint32_t e1 = sm[r0 + 2560 + 160];
                uint32_t e2 = sm[r0 + 2560 + 4];
                uint32_t e3 = sm[r0 + 2560 + 164];
                #pragma unroll
                for (int nf = 0; nf < 4; nf++) {
                    mma16816(acc[mf][nf][0], acc[mf][nf][1], acc[mf][nf][2], acc[mf][nf][3],
                             a0, a1, a2, a3, bh[nf][0], bh[nf][1]);
                    mma16816(acc[mf][nf][0], acc[mf][nf][1], acc[mf][nf][2], acc[mf][nf][3],
                             e0, e1, e2, e3, bh[nf][0], bh[nf][1]);
                    mma16816(acc[mf][nf][0], acc[mf][nf][1], acc[mf][nf][2], acc[mf][nf][3],
                             a0, a1, a2, a3, bl[nf][0], bl[nf][1]);
                }
            }
        }
        __syncthreads();
    }

    // ---- epilogue ----
    #pragma unroll
    for (int mf = 0; mf < 2; mf++) {
        #pragma unroll
        for (int r = 0; r < 4; r += 2) {
            int m = m0 + wm * 32 + mf * 16 + (r >> 1) * 8 + lr;
            if (m >= R_ROIS) continue;
            #pragma unroll
            for (int nf = 0; nf < 4; nf++) {
                int n = n0 + wn * 32 + nf * 8 + lc;
                float v0 = acc[mf][nf][r];
                float v1 = acc[mf][nf][r + 1];
                if (MODE == 0) {
                    float iv0 = rsqrtf(__ldg(&var[n]) + 0.001f);
                    float iv1 = rsqrtf(__ldg(&var[n + 1]) + 0.001f);
                    v0 = (v0 + __ldg(&bias[n])     - __ldg(&mean[n]))     * iv0 * __ldg(&gamma[n])     + __ldg(&beta[n]);
                    v1 = (v1 + __ldg(&bias[n + 1]) - __ldg(&mean[n + 1])) * iv1 * __ldg(&gamma[n + 1]) + __ldg(&beta[n + 1]);
                } else {
                    v0 = fmaxf(v0 + __ldg(&bias[n]), 0.0f);
                    v1 = fmaxf(v1 + __ldg(&bias[n + 1]), 0.0f);
                }
                float2 st; st.x = v0; st.y = v1;
                *(float2*)&Out[(size_t)m * HID + n] = st;
            }
        }
    }
}

__global__ __launch_bounds__(256)
void gemm_conv_kernel(const float* __restrict__ w,  const float* __restrict__ cb,
                      const float* __restrict__ g,  const float* __restrict__ be,
                      const float* __restrict__ mn, const float* __restrict__ vr)
{
    gemm_body<0>(g_pooled, w, KCONV, cb, g, be, mn, vr, g_y);
}
__global__ __launch_bounds__(256)
void gemm_fc1_kernel(const float* __restrict__ w, const float* __restrict__ b)
{
    gemm_body<1>(g_y, w, HID, b, nullptr, nullptr, nullptr, nullptr, g_h1);
}
__global__ __launch_bounds__(256)
void gemm_fc2_kernel(const float* __restrict__ w, const float* __restrict__ b)
{
    gemm_body<1>(g_h1, w, HID, b, nullptr, nullptr, nullptr, nullptr, g_h2);
}

// ---------------- heads: logits, softmax probs, bbox (unchanged from R2) ----------
__global__ void heads_kernel(const float* __restrict__ cls_w,
                             const float* __restrict__ cls_b,
                             const float* __restrict__ bbox_w,
                             const float* __restrict__ bbox_b,
                             float* __restrict__ out)
{
    int r = blockIdx.x;
    int t = threadIdx.x;   // 128 threads

    float acc[10];
    #pragma unroll
    for (int i = 0; i < 10; i++) acc[i] = 0.0f;

    const float* hrow = &g_h2[(size_t)r * HID];
    for (int k = t; k < HID; k += 128) {
        float h = hrow[k];
        acc[0] = fmaf(h, cls_w[k],        acc[0]);
        acc[1] = fmaf(h, cls_w[HID + k],  acc[1]);
        #pragma unroll
        for (int j = 0; j < 8; j++)
            acc[2 + j] = fmaf(h, bbox_w[(size_t)j * HID + k], acc[2 + j]);
    }

    #pragma unroll
    for (int off = 16; off > 0; off >>= 1)
        #pragma unroll
        for (int i = 0; i < 10; i++)
            acc[i] += __shfl_down_sync(0xffffffffu, acc[i], off);

    __shared__ float red[4][10];
    if ((t & 31) == 0)
        #pragma unroll
        for (int i = 0; i < 10; i++) red[t >> 5][i] = acc[i];
    __syncthreads();

    if (t == 0) {
        float s[10];
        #pragma unroll
        for (int i = 0; i < 10; i++)
            s[i] = red[0][i] + red[1][i] + red[2][i] + red[3][i];

        float l0 = s[0] + cls_b[0];
        float l1 = s[1] + cls_b[1];
        out[r * 2 + 0] = l0;
        out[r * 2 + 1] = l1;

        float mx = fmaxf(l0, l1);
        float e0 = expf(l0 - mx), e1 = expf(l1 - mx);
        float inv = 1.0f / (e0 + e1);
        out[2 * R_ROIS + r * 2 + 0] = e0 * inv;
        out[2 * R_ROIS + r * 2 + 1] = e1 * inv;

        #pragma unroll
        for (int j = 0; j < 8; j++)
            out[4 * R_ROIS + r * 8 + j] = s[2 + j] + bbox_b[j];
    }
}

// ---------------- launch ----------------
extern "C" void kernel_launch(void* const* d_in, const int* in_sizes, int n_in,
                              void* d_out, int out_size)
{
    const float* feat2   = (const float*)d_in[0];
    const float* feat3   = (const float*)d_in[1];
    const float* feat4   = (const float*)d_in[2];
    const float* feat5   = (const float*)d_in[3];
    const float* rois    = (const float*)d_in[4];
    const float* conv_w  = (const float*)d_in[5];
    const float* conv_b  = (const float*)d_in[6];
    const float* bn_g    = (const float*)d_in[7];
    const float* bn_b    = (const float*)d_in[8];
    const float* bn_m    = (const float*)d_in[9];
    const float* bn_v    = (const float*)d_in[10];
    const float* fc1_w   = (const float*)d_in[11];
    const float* fc1_b   = (const float*)d_in[12];
    const float* fc2_w   = (const float*)d_in[13];
    const float* fc2_b   = (const float*)d_in[14];
    const float* cls_w   = (const float*)d_in[15];
    const float* cls_b   = (const float*)d_in[16];
    const float* bbox_w  = (const float*)d_in[17];
    const float* bbox_b  = (const float*)d_in[18];
    float* out = (float*)d_out;

    // 1) ROI align -> fp32 pooled
    {
        const int total = R_ROIS * NCH * POOLP * POOLP;
        roi_align_kernel<<<(total + 255) / 256, 256>>>(feat2, feat3, feat4, feat5, rois);
    }

    // 2) GEMMs on tensor cores (grid: 16 N-tiles x 8 M-tiles = 128 CTAs)
    dim3 grid(HID / 64, MPAD / 128);
    gemm_conv_kernel<<<grid, 256>>>(conv_w, conv_b, bn_g, bn_b, bn_m, bn_v);
    gemm_fc1_kernel<<<grid, 256>>>(fc1_w, fc1_b);
    gemm_fc2_kernel<<<grid, 256>>>(fc2_w, fc2_b);

    // 3) heads
    heads_kernel<<<R_ROIS, 128>>>(cls_w, cls_b, bbox_w, bbox_b, out);
}

// round 10
// speedup vs baseline: 2.0064x; 1.5186x over previous
#include <cuda_runtime.h>
#include <cuda_bf16.h>
#include <math.h>
#include <stdint.h>

#define R_ROIS 1000
#define MPAD   1024
#define NCH    256
#define POOLP  7
#define KCONV  12544
#define HID    1024

// ---------------- scratch (static device globals) --------------------------------
__device__ __align__(16) float g_pooled[(size_t)MPAD * KCONV];  // rows 1000..1023 stay 0
__device__ __align__(16) float g_y [(size_t)MPAD * HID];
__device__ __align__(16) float g_h1[(size_t)MPAD * HID];
__device__ __align__(16) float g_h2[(size_t)MPAD * HID];

// ---------------- helpers ----------------
__device__ __forceinline__ void mma16816(float& c0, float& c1, float& c2, float& c3,
                                         uint32_t a0, uint32_t a1, uint32_t a2, uint32_t a3,
                                         uint32_t b0, uint32_t b1) {
    asm volatile("mma.sync.aligned.m16n8k16.row.col.f32.bf16.bf16.f32 "
        "{%0,%1,%2,%3}, {%4,%5,%6,%7}, {%8,%9}, {%0,%1,%2,%3};"
        : "+f"(c0), "+f"(c1), "+f"(c2), "+f"(c3)
        : "r"(a0), "r"(a1), "r"(a2), "r"(a3), "r"(b0), "r"(b1));
}
// split two fp32 into packed (hi, lo) bf16x2 registers; low half = first element
__device__ __forceinline__ void split_pack(float x, float y, uint32_t& hi, uint32_t& lo) {
    __nv_bfloat16 hx = __float2bfloat16(x);
    __nv_bfloat16 hy = __float2bfloat16(y);
    __nv_bfloat16 lx = __float2bfloat16(x - __bfloat162float(hx));
    __nv_bfloat16 ly = __float2bfloat16(y - __bfloat162float(hy));
    hi = (uint32_t)__bfloat16_as_ushort(hx) | ((uint32_t)__bfloat16_as_ushort(hy) << 16);
    lo = (uint32_t)__bfloat16_as_ushort(lx) | ((uint32_t)__bfloat16_as_ushort(ly) << 16);
}

// ---------------- ROI align (fp32 pooled) ----------------
__global__ void roi_align_kernel(const float* __restrict__ f2,
                                 const float* __restrict__ f3,
                                 const float* __restrict__ f4,
                                 const float* __restrict__ f5,
                                 const float* __restrict__ rois)
{
    int idx = blockIdx.x * blockDim.x + threadIdx.x;
    const int total = R_ROIS * NCH * POOLP * POOLP;
    if (idx >= total) return;

    int px = idx % POOLP;
    int py = (idx / POOLP) % POOLP;
    int c  = (idx / (POOLP * POOLP)) % NCH;
    int r  = idx / (NCH * POOLP * POOLP);

    float x1 = rois[r * 4 + 0];
    float y1 = rois[r * 4 + 1];
    float x2 = rois[r * 4 + 2];
    float y2 = rois[r * 4 + 3];

    float area = (y2 - y1) * (x2 - x1);
    float lf = rintf(log2f(sqrtf(area) * (1.0f / 224.0f))) + 4.0f;
    lf = fminf(fmaxf(lf, 2.0f), 5.0f);
    int lvl = (int)lf;

    const float* f = (lvl == 2) ? f2 : (lvl == 3) ? f3 : (lvl == 4) ? f4 : f5;
    int H = 256 >> (lvl - 2);

    const float inv = 1.0f / 1024.0f;
    float by1 = y1 * inv, bx1 = x1 * inv, by2 = y2 * inv, bx2 = x2 * inv;

    float ty = (float)py * (1.0f / 6.0f);
    float tx = (float)px * (1.0f / 6.0f);
    float Hm1 = (float)(H - 1);
    float ys = (by1 + (by2 - by1) * ty) * Hm1;
    float xs = (bx1 + (bx2 - bx1) * tx) * Hm1;

    bool valid = (ys >= 0.0f) && (ys <= Hm1) && (xs >= 0.0f) && (xs <= Hm1);

    float yf = floorf(ys), xf = floorf(xs);
    float wy = ys - yf,    wx = xs - xf;

    int y0  = min(max((int)yf,     0), H - 1);
    int y1i = min(max((int)yf + 1, 0), H - 1);
    int x0  = min(max((int)xf,     0), H - 1);
    int x1i = min(max((int)xf + 1, 0), H - 1);

    const float* fc = f + (size_t)c * H * H;
    float v00 = fc[y0  * H + x0 ];
    float v01 = fc[y0  * H + x1i];
    float v10 = fc[y1i * H + x0 ];
    float v11 = fc[y1i * H + x1i];

    float val = v00 * (1.0f - wy) * (1.0f - wx)
              + v01 * (1.0f - wy) * wx
              + v10 * wy * (1.0f - wx)
              + v11 * wy * wx;

    g_pooled[(size_t)r * KCONV + c * (POOLP * POOLP) + py * POOLP + px] =
        valid ? val : 0.0f;
}

// ---------------- HMMA GEMM, register-prefetch pipelined -------------------------
// C[m,n] = dot(A[m,:], B[n,:]); A,B fp32 row-major (A: [MPAD][K], B: [N][K]).
// Accumulates ah·bh + al·bh + ah·bl in fp32 (residual ~2^-16 relative).
// CTA tile 128Mx64N, K-tile 32. 256 threads = 8 warps (4M x 2N), warp tile 32x32.
// Pipeline: regs hold tile kt; store->sync; issue loads for kt+1; compute kt.
// smem words (uint32): Ahi@0 (row stride 20 words), Alo@2560, Bhi@5120, Blo@6400.
// MODE 0: batchnorm epilogue; MODE 1: relu(x + bias). Outputs fp32.
template<int MODE>
__device__ __forceinline__ void gemm_body(
    const float* __restrict__ A,
    const float* __restrict__ B,
    int K,
    const float* __restrict__ bias,
    const float* __restrict__ gamma, const float* __restrict__ beta,
    const float* __restrict__ mean,  const float* __restrict__ var,
    float* __restrict__ Out)
{
    __shared__ __align__(16) uint32_t sm[7680];   // 30720 bytes

    const int tid = threadIdx.x;
    const int wid = tid >> 5, l = tid & 31;
    const int wm = wid & 3, wn = wid >> 2;     // 4 M-warps x 2 N-warps
    const int lr = l >> 2, lc = (l & 3) * 2;   // groupID, tg*2

    const int m0 = blockIdx.y * 128;
    const int n0 = blockIdx.x * 64;
    const int NKT = K >> 5;

    // per-thread fixed load coordinates
    const int arow0 = tid >> 3, ach = tid & 7;          // A rows arow0 + 32*i
    const int brow0 = tid >> 3, bch = tid & 7;          // B rows brow0 + 32*i (i<2)
    const float* Abase = A + (size_t)(m0 + arow0) * K + ach * 4;
    const float* Bbase = B + (size_t)(n0 + brow0) * K + bch * 4;
    const size_t Astep = (size_t)32 * K;                // +32 rows
    const size_t Bstep = (size_t)32 * K;

    float acc[2][4][4];
    #pragma unroll
    for (int i = 0; i < 2; i++)
        #pragma unroll
        for (int j = 0; j < 4; j++)
            #pragma unroll
            for (int k = 0; k < 4; k++) acc[i][j][k] = 0.0f;

    // prefetch registers
    float4 pa[4], pb[2];
    #pragma unroll
    for (int i = 0; i < 4; i++) pa[i] = *(const float4*)(Abase + i * Astep);
    #pragma unroll
    for (int i = 0; i < 2; i++) pb[i] = *(const float4*)(Bbase + i * Bstep);

    for (int kt = 0; kt < NKT; ++kt) {
        // ---- store prefetched tile (split fp32 -> hi/lo bf16) ----
        #pragma unroll
        for (int i = 0; i < 4; i++) {
            uint32_t h0, l0, h1, l1;
            split_pack(pa[i].x, pa[i].y, h0, l0);
            split_pack(pa[i].z, pa[i].w, h1, l1);
            int w = (arow0 + i * 32) * 20 + ach * 2;
            *(uint2*)&sm[w]        = make_uint2(h0, h1);
            *(uint2*)&sm[w + 2560] = make_uint2(l0, l1);
        }
        #pragma unroll
        for (int i = 0; i < 2; i++) {
            uint32_t h0, l0, h1, l1;
            split_pack(pb[i].x, pb[i].y, h0, l0);
            split_pack(pb[i].z, pb[i].w, h1, l1);
            int w = 5120 + (brow0 + i * 32) * 20 + bch * 2;
            *(uint2*)&sm[w]        = make_uint2(h0, h1);
            *(uint2*)&sm[w + 1280] = make_uint2(l0, l1);
        }
        __syncthreads();

        // ---- issue next tile's global loads (latency overlapped with compute) ----
        if (kt + 1 < NKT) {
            const float* An = Abase + (size_t)(kt + 1) * 32;
            const float* Bn = Bbase + (size_t)(kt + 1) * 32;
            #pragma unroll
            for (int i = 0; i < 4; i++) pa[i] = *(const float4*)(An + i * Astep);
            #pragma unroll
            for (int i = 0; i < 2; i++) pb[i] = *(const float4*)(Bn + i * Bstep);
        }

        // ---- compute current tile from smem ----
        #pragma unroll
        for (int h = 0; h < 2; ++h) {
            uint32_t bh[4][2], bl[4][2];
            #pragma unroll
            for (int nf = 0; nf < 4; nf++) {
                int r0 = 5120 + (wn * 32 + nf * 8 + lr) * 20 + h * 8 + (lc >> 1);
                bh[nf][0] = sm[r0];
                bh[nf][1] = sm[r0 + 4];          // k + 8
                bl[nf][0] = sm[r0 + 1280];
                bl[nf][1] = sm[r0 + 1280 + 4];
            }
            #pragma unroll
            for (int mf = 0; mf < 2; mf++) {
                int r0 = (wm * 32 + mf * 16 + lr) * 20 + h * 8 + (lc >> 1);
                uint32_t a0 = sm[r0];
                uint32_t a1 = sm[r0 + 160];      // row + 8
                uint32_t a2 = sm[r0 + 4];        // k + 8
                uint32_t a3 = sm[r0 + 164];
                uint32_t e0 = sm[r0 + 2560];
                uint32_t e1 = sm[r0 + 2560 + 160];
                uint32_t e2 = sm[r0 + 2560 + 4];
                uint32_t e3 = sm[r0 + 2560 + 164];
                #pragma unroll
                for (int nf = 0; nf < 4; nf++) {
                    mma16816(acc[mf][nf][0], acc[mf][nf][1], acc[mf][nf][2], acc[mf][nf][3],
                             a0, a1, a2, a3, bh[nf][0], bh[nf][1]);
                    mma16816(acc[mf][nf][0], acc[mf][nf][1], acc[mf][nf][2], acc[mf][nf][3],
                             e0, e1, e2, e3, bh[nf][0], bh[nf][1]);
                    mma16816(acc[mf][nf][0], acc[mf][nf][1], acc[mf][nf][2], acc[mf][nf][3],
                             a0, a1, a2, a3, bl[nf][0], bl[nf][1]);
                }
            }
        }
        __syncthreads();
    }

    // ---- epilogue ----
    #pragma unroll
    for (int mf = 0; mf < 2; mf++) {
        #pragma unroll
        for (int r = 0; r < 4; r += 2) {
            int m = m0 + wm * 32 + mf * 16 + (r >> 1) * 8 + lr;
            if (m >= R_ROIS) continue;
            #pragma unroll
            for (int nf = 0; nf < 4; nf++) {
                int n = n0 + wn * 32 + nf * 8 + lc;
                float v0 = acc[mf][nf][r];
                float v1 = acc[mf][nf][r + 1];
                if (MODE == 0) {
                    float iv0 = rsqrtf(__ldg(&var[n]) + 0.001f);
                    float iv1 = rsqrtf(__ldg(&var[n + 1]) + 0.001f);
                    v0 = (v0 + __ldg(&bias[n])     - __ldg(&mean[n]))     * iv0 * __ldg(&gamma[n])     + __ldg(&beta[n]);
                    v1 = (v1 + __ldg(&bias[n + 1]) - __ldg(&mean[n + 1])) * iv1 * __ldg(&gamma[n + 1]) + __ldg(&beta[n + 1]);
                } else {
                    v0 = fmaxf(v0 + __ldg(&bias[n]), 0.0f);
                    v1 = fmaxf(v1 + __ldg(&bias[n + 1]), 0.0f);
                }
                float2 st; st.x = v0; st.y = v1;
                *(float2*)&Out[(size_t)m * HID + n] = st;
            }
        }
    }
}

__global__ __launch_bounds__(256)
void gemm_conv_kernel(const float* __restrict__ w,  const float* __restrict__ cb,
                      const float* __restrict__ g,  const float* __restrict__ be,
                      const float* __restrict__ mn, const float* __restrict__ vr)
{
    gemm_body<0>(g_pooled, w, KCONV, cb, g, be, mn, vr, g_y);
}
__global__ __launch_bounds__(256)
void gemm_fc1_kernel(const float* __restrict__ w, const float* __restrict__ b)
{
    gemm_body<1>(g_y, w, HID, b, nullptr, nullptr, nullptr, nullptr, g_h1);
}
__global__ __launch_bounds__(256)
void gemm_fc2_kernel(const float* __restrict__ w, const float* __restrict__ b)
{
    gemm_body<1>(g_h1, w, HID, b, nullptr, nullptr, nullptr, nullptr, g_h2);
}

// ---------------- heads: logits, softmax probs, bbox ----------------
__global__ void heads_kernel(const float* __restrict__ cls_w,
                             const float* __restrict__ cls_b,
                             const float* __restrict__ bbox_w,
                             const float* __restrict__ bbox_b,
                             float* __restrict__ out)
{
    int r = blockIdx.x;
    int t = threadIdx.x;   // 128 threads

    float acc[10];
    #pragma unroll
    for (int i = 0; i < 10; i++) acc[i] = 0.0f;

    const float* hrow = &g_h2[(size_t)r * HID];
    for (int k = t; k < HID; k += 128) {
        float h = hrow[k];
        acc[0] = fmaf(h, cls_w[k],        acc[0]);
        acc[1] = fmaf(h, cls_w[HID + k],  acc[1]);
        #pragma unroll
        for (int j = 0; j < 8; j++)
            acc[2 + j] = fmaf(h, bbox_w[(size_t)j * HID + k], acc[2 + j]);
    }

    #pragma unroll
    for (int off = 16; off > 0; off >>= 1)
        #pragma unroll
        for (int i = 0; i < 10; i++)
            acc[i] += __shfl_down_sync(0xffffffffu, acc[i], off);

    __shared__ float red[4][10];
    if ((t & 31) == 0)
        #pragma unroll
        for (int i = 0; i < 10; i++) red[t >> 5][i] = acc[i];
    __syncthreads();

    if (t == 0) {
        float s[10];
        #pragma unroll
        for (int i = 0; i < 10; i++)
            s[i] = red[0][i] + red[1][i] + red[2][i] + red[3][i];

        float l0 = s[0] + cls_b[0];
        float l1 = s[1] + cls_b[1];
        out[r * 2 + 0] = l0;
        out[r * 2 + 1] = l1;

        float mx = fmaxf(l0, l1);
        float e0 = expf(l0 - mx), e1 = expf(l1 - mx);
        float inv = 1.0f / (e0 + e1);
        out[2 * R_ROIS + r * 2 + 0] = e0 * inv;
        out[2 * R_ROIS + r * 2 + 1] = e1 * inv;

        #pragma unroll
        for (int j = 0; j < 8; j++)
            out[4 * R_ROIS + r * 8 + j] = s[2 + j] + bbox_b[j];
    }
}

// ---------------- launch ----------------
extern "C" void kernel_launch(void* const* d_in, const int* in_sizes, int n_in,
                              void* d_out, int out_size)
{
    const float* feat2   = (const float*)d_in[0];
    const float* feat3   = (const float*)d_in[1];
    const float* feat4   = (const float*)d_in[2];
    const float* feat5   = (const float*)d_in[3];
    const float* rois    = (const float*)d_in[4];
    const float* conv_w  = (const float*)d_in[5];
    const float* conv_b  = (const float*)d_in[6];
    const float* bn_g    = (const float*)d_in[7];
    const float* bn_b    = (const float*)d_in[8];
    const float* bn_m    = (const float*)d_in[9];
    const float* bn_v    = (const float*)d_in[10];
    const float* fc1_w   = (const float*)d_in[11];
    const float* fc1_b   = (const float*)d_in[12];
    const float* fc2_w   = (const float*)d_in[13];
    const float* fc2_b   = (const float*)d_in[14];
    const float* cls_w   = (const float*)d_in[15];
    const float* cls_b   = (const float*)d_in[16];
    const float* bbox_w  = (const float*)d_in[17];
    const float* bbox_b  = (const float*)d_in[18];
    float* out = (float*)d_out;

    // 1) ROI align -> fp32 pooled
    {
        const int total = R_ROIS * NCH * POOLP * POOLP;
        roi_align_kernel<<<(total + 255) / 256, 256>>>(feat2, feat3, feat4, feat5, rois);
    }

    // 2) GEMMs on tensor cores (grid: 16 N-tiles x 8 M-tiles = 128 CTAs)
    dim3 grid(HID / 64, MPAD / 128);
    gemm_conv_kernel<<<grid, 256>>>(conv_w, conv_b, bn_g, bn_b, bn_m, bn_v);
    gemm_fc1_kernel<<<grid, 256>>>(fc1_w, fc1_b);
    gemm_fc2_kernel<<<grid, 256>>>(fc2_w, fc2_b);

    // 3) heads
    heads_kernel<<<R_ROIS, 128>>>(cls_w, cls_b, bbox_w, bbox_b, out);
}

// round 11
// speedup vs baseline: 2.3236x; 1.1581x over previous
#include <cuda_runtime.h>
#include <cuda_bf16.h>
#include <math.h>
#include <stdint.h>

#define R_ROIS 1000
#define MPAD   1024
#define NCH    256
#define POOLP  7
#define KCONV  12544
#define HID    1024

// ---------------- scratch (static device globals; ~63MB total, proven envelope) --
// activations stored PACKED: one uint32 per element = (hi_bf16 << 16) | lo_bf16
__device__ __align__(16) uint32_t g_pooled[(size_t)MPAD * KCONV];  // rows>=1000 stay 0
__device__ __align__(16) uint32_t g_y [(size_t)MPAD * HID];
__device__ __align__(16) uint32_t g_h1[(size_t)MPAD * HID];
__device__ __align__(16) float    g_h2[(size_t)MPAD * HID];

// ---------------- helpers ----------------
__device__ __forceinline__ void mma16816(float& c0, float& c1, float& c2, float& c3,
                                         uint32_t a0, uint32_t a1, uint32_t a2, uint32_t a3,
                                         uint32_t b0, uint32_t b1) {
    asm volatile("mma.sync.aligned.m16n8k16.row.col.f32.bf16.bf16.f32 "
        "{%0,%1,%2,%3}, {%4,%5,%6,%7}, {%8,%9}, {%0,%1,%2,%3};"
        : "+f"(c0), "+f"(c1), "+f"(c2), "+f"(c3)
        : "r"(a0), "r"(a1), "r"(a2), "r"(a3), "r"(b0), "r"(b1));
}
// split two fp32 into packed (hi, lo) bf16x2 registers; low half = first element
__device__ __forceinline__ void split_pack(float x, float y, uint32_t& hi, uint32_t& lo) {
    __nv_bfloat16 hx = __float2bfloat16(x);
    __nv_bfloat16 hy = __float2bfloat16(y);
    __nv_bfloat16 lx = __float2bfloat16(x - __bfloat162float(hx));
    __nv_bfloat16 ly = __float2bfloat16(y - __bfloat162float(hy));
    hi = (uint32_t)__bfloat16_as_ushort(hx) | ((uint32_t)__bfloat16_as_ushort(hy) << 16);
    lo = (uint32_t)__bfloat16_as_ushort(lx) | ((uint32_t)__bfloat16_as_ushort(ly) << 16);
}
// pack one fp32 into (hi<<16)|lo word
__device__ __forceinline__ uint32_t pack1(float v) {
    __nv_bfloat16 h = __float2bfloat16(v);
    __nv_bfloat16 l = __float2bfloat16(v - __bfloat162float(h));
    return ((uint32_t)__bfloat16_as_ushort(h) << 16) | (uint32_t)__bfloat16_as_ushort(l);
}

// ---------------- ROI align (writes packed hi/lo) ----------------
__global__ void roi_align_kernel(const float* __restrict__ f2,
                                 const float* __restrict__ f3,
                                 const float* __restrict__ f4,
                                 const float* __restrict__ f5,
                                 const float* __restrict__ rois)
{
    int idx = blockIdx.x * blockDim.x + threadIdx.x;
    const int total = R_ROIS * NCH * POOLP * POOLP;
    if (idx >= total) return;

    int px = idx % POOLP;
    int py = (idx / POOLP) % POOLP;
    int c  = (idx / (POOLP * POOLP)) % NCH;
    int r  = idx / (NCH * POOLP * POOLP);

    float x1 = rois[r * 4 + 0];
    float y1 = rois[r * 4 + 1];
    float x2 = rois[r * 4 + 2];
    float y2 = rois[r * 4 + 3];

    float area = (y2 - y1) * (x2 - x1);
    float lf = rintf(log2f(sqrtf(area) * (1.0f / 224.0f))) + 4.0f;
    lf = fminf(fmaxf(lf, 2.0f), 5.0f);
    int lvl = (int)lf;

    const float* f = (lvl == 2) ? f2 : (lvl == 3) ? f3 : (lvl == 4) ? f4 : f5;
    int H = 256 >> (lvl - 2);

    const float inv = 1.0f / 1024.0f;
    float by1 = y1 * inv, bx1 = x1 * inv, by2 = y2 * inv, bx2 = x2 * inv;

    float ty = (float)py * (1.0f / 6.0f);
    float tx = (float)px * (1.0f / 6.0f);
    float Hm1 = (float)(H - 1);
    float ys = (by1 + (by2 - by1) * ty) * Hm1;
    float xs = (bx1 + (bx2 - bx1) * tx) * Hm1;

    bool valid = (ys >= 0.0f) && (ys <= Hm1) && (xs >= 0.0f) && (xs <= Hm1);

    float yf = floorf(ys), xf = floorf(xs);
    float wy = ys - yf,    wx = xs - xf;

    int y0  = min(max((int)yf,     0), H - 1);
    int y1i = min(max((int)yf + 1, 0), H - 1);
    int x0  = min(max((int)xf,     0), H - 1);
    int x1i = min(max((int)xf + 1, 0), H - 1);

    const float* fc = f + (size_t)c * H * H;
    float v00 = fc[y0  * H + x0 ];
    float v01 = fc[y0  * H + x1i];
    float v10 = fc[y1i * H + x0 ];
    float v11 = fc[y1i * H + x1i];

    float val = v00 * (1.0f - wy) * (1.0f - wx)
              + v01 * (1.0f - wy) * wx
              + v10 * wy * (1.0f - wx)
              + v11 * wy * wx;
    val = valid ? val : 0.0f;

    g_pooled[(size_t)r * KCONV + c * (POOLP * POOLP) + py * POOLP + px] = pack1(val);
}

// ---------------- HMMA GEMM: packed-A, double-buffered, 64x64 CTA tile ----------
// C[m,n] = dot(A[m,:], B[n,:]); A packed uint32 [MPAD][K], B fp32 [N][K].
// Accumulates ah·bh + al·bh + ah·bl in fp32 (residual ~2^-16 relative).
// 128 threads = 4 warps (2M x 2N), warp tile 32x32, K-tile 32.
// smem: 2 buffers x 5120 words; per buffer: Ahi@0, Alo@1280, Bhi@2560, Blo@3840;
// row stride 20 words. One __syncthreads per K-tile (double buffer).
// MODE 0: BN -> packed out. MODE 1: relu -> packed out. MODE 2: relu -> fp32 out.
template<int MODE>
__device__ __forceinline__ void gemm_body(
    const uint32_t* __restrict__ Ap,
    const float* __restrict__ B,
    int K,
    const float* __restrict__ bias,
    const float* __restrict__ gamma, const float* __restrict__ beta,
    const float* __restrict__ mean,  const float* __restrict__ var,
    uint32_t* __restrict__ OutP,
    float* __restrict__ OutF)
{
    __shared__ __align__(16) uint32_t sm[10240];   // 40KB: two 5120-word buffers

    const int tid = threadIdx.x;
    const int wid = tid >> 5, l = tid & 31;
    const int wm = wid & 1, wn = wid >> 1;     // 2 M-warps x 2 N-warps
    const int lr = l >> 2, lc = (l & 3) * 2;

    const int m0 = blockIdx.y * 64;
    const int n0 = blockIdx.x * 64;
    const int NKT = K >> 5;

    // per-thread load coords: rows row0 + 16*i (i<4), chunk ch (4 elements)
    const int row0 = tid >> 3, ch = tid & 7;
    const uint32_t* Abase = Ap + (size_t)(m0 + row0) * K + ch * 4;
    const float*    Bbase = B  + (size_t)(n0 + row0) * K + ch * 4;
    const size_t step16 = (size_t)16 * K;

    float acc[2][4][4];
    #pragma unroll
    for (int i = 0; i < 2; i++)
        #pragma unroll
        for (int j = 0; j < 4; j++)
            #pragma unroll
            for (int k = 0; k < 4; k++) acc[i][j][k] = 0.0f;

    // prefetch tile 0
    uint4  pa[4];
    float4 pb[4];
    #pragma unroll
    for (int i = 0; i < 4; i++) pa[i] = *(const uint4*)(Abase + i * step16);
    #pragma unroll
    for (int i = 0; i < 4; i++) pb[i] = *(const float4*)(Bbase + i * step16);

    for (int kt = 0; kt < NKT; ++kt) {
        const int bo = (kt & 1) * 5120;

        // ---- store tile kt: A via byte_perm unpack, B via split ----
        #pragma unroll
        for (int i = 0; i < 4; i++) {
            uint32_t hi0 = __byte_perm(pa[i].x, pa[i].y, 0x7632);
            uint32_t lo0 = __byte_perm(pa[i].x, pa[i].y, 0x5410);
            uint32_t hi1 = __byte_perm(pa[i].z, pa[i].w, 0x7632);
            uint32_t lo1 = __byte_perm(pa[i].z, pa[i].w, 0x5410);
            int w = bo + (row0 + i * 16) * 20 + ch * 2;
            *(uint2*)&sm[w]        = make_uint2(hi0, hi1);
            *(uint2*)&sm[w + 1280] = make_uint2(lo0, lo1);
        }
        #pragma unroll
        for (int i = 0; i < 4; i++) {
            uint32_t h0, l0, h1, l1;
            split_pack(pb[i].x, pb[i].y, h0, l0);
            split_pack(pb[i].z, pb[i].w, h1, l1);
            int w = bo + 2560 + (row0 + i * 16) * 20 + ch * 2;
            *(uint2*)&sm[w]        = make_uint2(h0, h1);
            *(uint2*)&sm[w + 1280] = make_uint2(l0, l1);
        }
        __syncthreads();

        // ---- issue next tile's global loads (overlap with compute) ----
        if (kt + 1 < NKT) {
            const uint32_t* An = Abase + (size_t)(kt + 1) * 32;
            const float*    Bn = Bbase + (size_t)(kt + 1) * 32;
            #pragma unroll
            for (int i = 0; i < 4; i++) pa[i] = *(const uint4*)(An + i * step16);
            #pragma unroll
            for (int i = 0; i < 4; i++) pb[i] = *(const float4*)(Bn + i * step16);
        }

        // ---- compute tile kt from buffer bo ----
        #pragma unroll
        for (int h = 0; h < 2; ++h) {
            uint32_t bh[4][2], bl[4][2];
            #pragma unroll
            for (int nf = 0; nf < 4; nf++) {
                int r0 = bo + 2560 + (wn * 32 + nf * 8 + lr) * 20 + h * 8 + (lc >> 1);
                bh[nf][0] = sm[r0];
                bh[nf][1] = sm[r0 + 4];          // k + 8
                bl[nf][0] = sm[r0 + 1280];
                bl[nf][1] = sm[r0 + 1280 + 4];
            }
            #pragma unroll
            for (int mf = 0; mf < 2; mf++) {
                int r0 = bo + (wm * 32 + mf * 16 + lr) * 20 + h * 8 + (lc >> 1);
                uint32_t a0 = sm[r0];
                uint32_t a1 = sm[r0 + 160];      // row + 8
                uint32_t a2 = sm[r0 + 4];        // k + 8
                uint32_t a3 = sm[r0 + 164];
                uint32_t e0 = sm[r0 + 1280];
                uint32_t e1 = sm[r0 + 1280 + 160];
                uint32_t e2 = sm[r0 + 1280 + 4];
                uint32_t e3 = sm[r0 + 1280 + 164];
                #pragma unroll
                for (int nf = 0; nf < 4; nf++) {
                    mma16816(acc[mf][nf][0], acc[mf][nf][1], acc[mf][nf][2], acc[mf][nf][3],
                             a0, a1, a2, a3, bh[nf][0], bh[nf][1]);
                    mma16816(acc[mf][nf][0], acc[mf][nf][1], acc[mf][nf][2], acc[mf][nf][3],
                             e0, e1, e2, e3, bh[nf][0], bh[nf][1]);
                    mma16816(acc[mf][nf][0], acc[mf][nf][1], acc[mf][nf][2], acc[mf][nf][3],
                             a0, a1, a2, a3, bl[nf][0], bl[nf][1]);
                }
            }
        }
    }

    // ---- epilogue ----
    #pragma unroll
    for (int mf = 0; mf < 2; mf++) {
        #pragma unroll
        for (int r = 0; r < 4; r += 2) {
            int m = m0 + wm * 32 + mf * 16 + (r >> 1) * 8 + lr;
            if (m >= R_ROIS) continue;
            #pragma unroll
            for (int nf = 0; nf < 4; nf++) {
                int n = n0 + wn * 32 + nf * 8 + lc;
                float v0 = acc[mf][nf][r];
                float v1 = acc[mf][nf][r + 1];
                if (MODE == 0) {
                    float iv0 = rsqrtf(__ldg(&var[n]) + 0.001f);
                    float iv1 = rsqrtf(__ldg(&var[n + 1]) + 0.001f);
                    v0 = (v0 + __ldg(&bias[n])     - __ldg(&mean[n]))     * iv0 * __ldg(&gamma[n])     + __ldg(&beta[n]);
                    v1 = (v1 + __ldg(&bias[n + 1]) - __ldg(&mean[n + 1])) * iv1 * __ldg(&gamma[n + 1]) + __ldg(&beta[n + 1]);
                } else {
                    v0 = fmaxf(v0 + __ldg(&bias[n]), 0.0f);
                    v1 = fmaxf(v1 + __ldg(&bias[n + 1]), 0.0f);
                }
                if (MODE <= 1) {
                    *(uint2*)&OutP[(size_t)m * HID + n] = make_uint2(pack1(v0), pack1(v1));
                } else {
                    float2 st; st.x = v0; st.y = v1;
                    *(float2*)&OutF[(size_t)m * HID + n] = st;
                }
            }
        }
    }
}

__global__ __launch_bounds__(128)
void gemm_conv_kernel(const float* __restrict__ w,  const float* __restrict__ cb,
                      const float* __restrict__ g,  const float* __restrict__ be,
                      const float* __restrict__ mn, const float* __restrict__ vr)
{
    gemm_body<0>(g_pooled, w, KCONV, cb, g, be, mn, vr, g_y, nullptr);
}
__global__ __launch_bounds__(128)
void gemm_fc1_kernel(const float* __restrict__ w, const float* __restrict__ b)
{
    gemm_body<1>(g_y, w, HID, b, nullptr, nullptr, nullptr, nullptr, g_h1, nullptr);
}
__global__ __launch_bounds__(128)
void gemm_fc2_kernel(const float* __restrict__ w, const float* __restrict__ b)
{
    gemm_body<2>(g_h1, w, HID, b, nullptr, nullptr, nullptr, nullptr, nullptr, g_h2);
}

// ---------------- heads: logits, softmax probs, bbox ----------------
__global__ void heads_kernel(const float* __restrict__ cls_w,
                             const float* __restrict__ cls_b,
                             const float* __restrict__ bbox_w,
                             const float* __restrict__ bbox_b,
                             float* __restrict__ out)
{
    int r = blockIdx.x;
    int t = threadIdx.x;   // 128 threads

    float acc[10];
    #pragma unroll
    for (int i = 0; i < 10; i++) acc[i] = 0.0f;

    const float* hrow = &g_h2[(size_t)r * HID];
    for (int k = t; k < HID; k += 128) {
        float h = hrow[k];
        acc[0] = fmaf(h, cls_w[k],        acc[0]);
        acc[1] = fmaf(h, cls_w[HID + k],  acc[1]);
        #pragma unroll
        for (int j = 0; j < 8; j++)
            acc[2 + j] = fmaf(h, bbox_w[(size_t)j * HID + k], acc[2 + j]);
    }

    #pragma unroll
    for (int off = 16; off > 0; off >>= 1)
        #pragma unroll
        for (int i = 0; i < 10; i++)
            acc[i] += __shfl_down_sync(0xffffffffu, acc[i], off);

    __shared__ float red[4][10];
    if ((t & 31) == 0)
        #pragma unroll
        for (int i = 0; i < 10; i++) red[t >> 5][i] = acc[i];
    __syncthreads();

    if (t == 0) {
        float s[10];
        #pragma unroll
        for (int i = 0; i < 10; i++)
            s[i] = red[0][i] + red[1][i] + red[2][i] + red[3][i];

        float l0 = s[0] + cls_b[0];
        float l1 = s[1] + cls_b[1];
        out[r * 2 + 0] = l0;
        out[r * 2 + 1] = l1;

        float mx = fmaxf(l0, l1);
        float e0 = expf(l0 - mx), e1 = expf(l1 - mx);
        float inv = 1.0f / (e0 + e1);
        out[2 * R_ROIS + r * 2 + 0] = e0 * inv;
        out[2 * R_ROIS + r * 2 + 1] = e1 * inv;

        #pragma unroll
        for (int j = 0; j < 8; j++)
            out[4 * R_ROIS + r * 8 + j] = s[2 + j] + bbox_b[j];
    }
}

// ---------------- launch ----------------
extern "C" void kernel_launch(void* const* d_in, const int* in_sizes, int n_in,
                              void* d_out, int out_size)
{
    const float* feat2   = (const float*)d_in[0];
    const float* feat3   = (const float*)d_in[1];
    const float* feat4   = (const float*)d_in[2];
    const float* feat5   = (const float*)d_in[3];
    const float* rois    = (const float*)d_in[4];
    const float* conv_w  = (const float*)d_in[5];
    const float* conv_b  = (const float*)d_in[6];
    const float* bn_g    = (const float*)d_in[7];
    const float* bn_b    = (const float*)d_in[8];
    const float* bn_m    = (const float*)d_in[9];
    const float* bn_v    = (const float*)d_in[10];
    const float* fc1_w   = (const float*)d_in[11];
    const float* fc1_b   = (const float*)d_in[12];
    const float* fc2_w   = (const float*)d_in[13];
    const float* fc2_b   = (const float*)d_in[14];
    const float* cls_w   = (const float*)d_in[15];
    const float* cls_b   = (const float*)d_in[16];
    const float* bbox_w  = (const float*)d_in[17];
    const float* bbox_b  = (const float*)d_in[18];
    float* out = (float*)d_out;

    // 1) ROI align -> packed pooled
    {
        const int total = R_ROIS * NCH * POOLP * POOLP;
        roi_align_kernel<<<(total + 255) / 256, 256>>>(feat2, feat3, feat4, feat5, rois);
    }

    // 2) GEMMs on tensor cores (grid: 16 N-tiles x 16 M-tiles = 256 CTAs)
    dim3 grid(HID / 64, MPAD / 64);
    gemm_conv_kernel<<<grid, 128>>>(conv_w, conv_b, bn_g, bn_b, bn_m, bn_v);
    gemm_fc1_kernel<<<grid, 128>>>(fc1_w, fc1_b);
    gemm_fc2_kernel<<<grid, 128>>>(fc2_w, fc2_b);

    // 3) heads
    heads_kernel<<<R_ROIS, 128>>>(cls_w, cls_b, bbox_w, bbox_b, out);
}